// round 14
// baseline (speedup 1.0000x reference)
#include <cuda_runtime.h>
#include <cuda_fp16.h>
#include <cstddef>
#include <cstdint>

// Problem constants
#define BB  4
#define SSQ 2048
#define DDm 1024
#define HHn 16
#define DHH 64
#define FFd 4096
#define BSr (BB*SSQ)      // 8192 rows
#define EPSLN 1e-5f

// ---------------- scratch (device globals; allocation-free) ----------------
__device__ float g_y1 [BSr*DDm];
__device__ float g_y2 [BSr*DDm];

__device__ __half g_src16[BSr*DDm];
__device__ __half g_q16  [BSr*DDm];
__device__ __half g_k16  [BSr*DDm];
__device__ __half g_vT16 [(size_t)DDm*BSr];   // [n=h*64+dh][m=b*2048+s]
__device__ __half g_ctx16[BSr*DDm];
__device__ __half g_x16  [BSr*DDm];
__device__ __half g_h16  [(size_t)BSr*FFd];

__device__ __half g_wqT[DDm*DDm];
__device__ __half g_wkT[DDm*DDm];
__device__ __half g_wvT[DDm*DDm];
__device__ __half g_woT[DDm*DDm];
__device__ __half g_w1T[(size_t)DDm*FFd];
__device__ __half g_w2T[(size_t)DDm*FFd];

// ---------------- asm helpers -----------------------------------------------
#define CP_ASYNC16(dst, src) \
    asm volatile("cp.async.cg.shared.global [%0], [%1], 16;\n" :: "r"(dst), "l"(src))
#define CP_COMMIT() asm volatile("cp.async.commit_group;\n" ::)
#define CP_WAIT1()  asm volatile("cp.async.wait_group 1;\n" ::)

#define MMA16816(d, a, b0, b1) \
    asm volatile("mma.sync.aligned.m16n8k16.row.col.f32.f16.f16.f32 " \
        "{%0,%1,%2,%3},{%4,%5,%6,%7},{%8,%9},{%0,%1,%2,%3};\n" \
        : "+f"(d[0]), "+f"(d[1]), "+f"(d[2]), "+f"(d[3]) \
        : "r"(a[0]), "r"(a[1]), "r"(a[2]), "r"(a[3]), "r"(b0), "r"(b1))

__device__ __forceinline__ uint32_t smem_u32(const void* p) {
    uint32_t a;
    asm("{ .reg .u64 t; cvta.to.shared.u64 t, %1; cvt.u32.u64 %0, t; }" : "=r"(a) : "l"(p));
    return a;
}

// ---------------- fp16 HGEMM: C[M,N] = A16[M,K] @ Bt16[N,K]^T ---------------
// CTA 128x128, 8 warps of 32x64, BK=32, 3-stage cp.async ring (one sync/iter),
// scalar-LDS fragments.  NOW 3 CTAs/SM (launch_bounds(256,3), regs <= 85).
// RES: 0 none, 1 f32 res, 2 fp16 res.  OUT16T: smem-staged transposed store.
#define SROW 40
#define HBUF 20480
#define HG_SMEM (3 * HBUF)
template<int RELU, int RES, int OUT32, int OUT16, int OUT16T>
__global__ __launch_bounds__(256, 3)
void hgemm_k(const __half* __restrict__ A, const __half* __restrict__ Bt,
             const float* __restrict__ bias, const void* __restrict__ res,
             float* __restrict__ C32, __half* __restrict__ C16,
             int M, int N, int K)
{
    extern __shared__ __half smx[];
    const uint32_t sb = smem_u32(smx);

    const int tid  = threadIdx.x;
    const int warp = tid >> 5;
    const int lane = tid & 31;
    const int wm = (warp >> 1) * 32;
    const int wn = (warp & 1) * 64;
    const int bm = blockIdx.y * 128;
    const int bn = blockIdx.x * 128;

    const int lrow  = tid >> 1;
    const int lcolh = (tid & 1) * 16;

    const __half* Ag = A  + (size_t)(bm + lrow) * K + lcolh;
    const __half* Bg = Bt + (size_t)(bn + lrow) * K + lcolh;

    const uint32_t saA = sb + lrow * 80 + (tid & 1) * 32;
    const uint32_t saB = saA + 10240;

    float acc[2][8][4];
#pragma unroll
    for (int mt = 0; mt < 2; mt++)
#pragma unroll
        for (int nt = 0; nt < 8; nt++)
#pragma unroll
            for (int i = 0; i < 4; i++) acc[mt][nt][i] = 0.0f;

    const int r  = lane >> 2;
    const int cb = lane & 3;
    const int niter = K >> 5;

#pragma unroll
    for (int ch = 0; ch < 2; ch++) {
        uint32_t bo = (uint32_t)ch * HBUF;
        int k0 = ch << 5;
        CP_ASYNC16(saA + bo,      Ag + k0);
        CP_ASYNC16(saA + bo + 16, Ag + k0 + 8);
        CP_ASYNC16(saB + bo,      Bg + k0);
        CP_ASYNC16(saB + bo + 16, Bg + k0 + 8);
        CP_COMMIT();
    }

    int buf = 0;
    for (int kt = 0; kt < niter; kt++) {
        CP_WAIT1();
        __syncthreads();

        if (kt + 2 < niter) {
            int lb = buf + 2; if (lb >= 3) lb -= 3;
            uint32_t bo = (uint32_t)lb * HBUF;
            int k0 = (kt + 2) << 5;
            CP_ASYNC16(saA + bo,      Ag + k0);
            CP_ASYNC16(saA + bo + 16, Ag + k0 + 8);
            CP_ASYNC16(saB + bo,      Bg + k0);
            CP_ASYNC16(saB + bo + 16, Bg + k0 + 8);
        }
        CP_COMMIT();

        const uint32_t* Ab = (const uint32_t*)(smx + (size_t)buf * (HBUF / 2));
        const uint32_t* Bb = Ab + 2560;
#pragma unroll
        for (int s = 0; s < 2; s++) {
            uint32_t af[2][4];
#pragma unroll
            for (int mt = 0; mt < 2; mt++) {
                int base = (wm + mt * 16 + r) * 20 + s * 8 + cb;
                af[mt][0] = Ab[base];
                af[mt][1] = Ab[base + 160];
                af[mt][2] = Ab[base + 4];
                af[mt][3] = Ab[base + 164];
            }
#pragma unroll
            for (int nt = 0; nt < 8; nt++) {
                int nb = (wn + nt * 8 + r) * 20 + s * 8 + cb;
                uint32_t b0 = Bb[nb];
                uint32_t b1 = Bb[nb + 4];
                MMA16816(acc[0][nt], af[0], b0, b1);
                MMA16816(acc[1][nt], af[1], b0, b1);
            }
        }
        if (++buf == 3) buf = 0;
    }

    const float* resf = (const float*)res;
    const __half* resh = (const __half*)res;

    if (OUT16T) {
        __syncthreads();
        __half* st = smx;
#pragma unroll
        for (int mt = 0; mt < 2; mt++) {
#pragma unroll
            for (int hh = 0; hh < 2; hh++) {
                int rl = wm + mt * 16 + r + hh * 8;
#pragma unroll
                for (int nt = 0; nt < 8; nt++) {
                    int cl = wn + nt * 8 + cb * 2;
                    float v0 = acc[mt][nt][hh * 2 + 0] + bias[bn + cl];
                    float v1 = acc[mt][nt][hh * 2 + 1] + bias[bn + cl + 1];
                    st[cl * 136 + rl]       = __float2half_rn(v0);
                    st[(cl + 1) * 136 + rl] = __float2half_rn(v1);
                }
            }
        }
        __syncthreads();
        const int c16 = tid >> 4;
        const int rr  = (tid & 15) * 8;
#pragma unroll
        for (int p = 0; p < 8; p++) {
            int c = c16 + p * 16;
            *(float4*)&C16[(size_t)(bn + c) * M + bm + rr] =
                *(const float4*)&st[c * 136 + rr];
        }
        return;
    }

#pragma unroll
    for (int mt = 0; mt < 2; mt++) {
#pragma unroll
        for (int hh = 0; hh < 2; hh++) {
            int row = bm + wm + mt * 16 + r + hh * 8;
#pragma unroll
            for (int nt = 0; nt < 8; nt++) {
                int col = bn + wn + nt * 8 + cb * 2;
                float v0 = acc[mt][nt][hh * 2 + 0] + bias[col];
                float v1 = acc[mt][nt][hh * 2 + 1] + bias[col + 1];
                if (RES == 1) {
                    float2 rv = *(const float2*)&resf[(size_t)row * N + col];
                    v0 += rv.x; v1 += rv.y;
                }
                if (RES == 2) {
                    __half2 rh = *(const __half2*)&resh[(size_t)row * N + col];
                    float2 rv = __half22float2(rh);
                    v0 += rv.x; v1 += rv.y;
                }
                if (RELU) { v0 = fmaxf(v0, 0.0f); v1 = fmaxf(v1, 0.0f); }
                if (OUT32)
                    *(float2*)&C32[(size_t)row * N + col] = make_float2(v0, v1);
                if (OUT16)
                    *(__half2*)&C16[(size_t)row * N + col] = __floats2half2_rn(v0, v1);
            }
        }
    }
}

// ---------------- fused prep: src conv + all 6 weight transposes ------------
__global__ __launch_bounds__(256)
void prep_k(const float* __restrict__ src, __half* __restrict__ src16,
            const float* __restrict__ Wq, __half* __restrict__ wqT,
            const float* __restrict__ Wk, __half* __restrict__ wkT,
            const float* __restrict__ Wv, __half* __restrict__ wvT,
            const float* __restrict__ Wo, __half* __restrict__ woT,
            const float* __restrict__ W1, __half* __restrict__ w1T,
            const float* __restrict__ W2, __half* __restrict__ w2T)
{
    __shared__ float t[64][33];
    const int tid = threadIdx.x;
    int b = blockIdx.x;

    if (b < 8192) {
        int i = b * 256 + tid;
        float4 v = ((const float4*)src)[i];
        __half2* o = (__half2*)src16;
        o[i * 2 + 0] = __floats2half2_rn(v.x, v.y);
        o[i * 2 + 1] = __floats2half2_rn(v.z, v.w);
        return;
    }
    b -= 8192;

    const float* inp; __half* outp; int Kd, Nd;
    if (b < 512)            { inp = Wq; outp = wqT; Kd = DDm; Nd = DHH; }
    else if (b < 1024)      { b -= 512;  inp = Wk; outp = wkT; Kd = DDm; Nd = DHH; }
    else if (b < 1536)      { b -= 1024; inp = Wv; outp = wvT; Kd = DDm; Nd = DHH; }
    else if (b < 2048)      { b -= 1536; inp = Wo; outp = woT; Kd = DDm; Nd = DDm; }
    else if (b < 4096)      { b -= 2048; inp = W1; outp = w1T; Kd = DDm; Nd = FFd; }
    else                    { b -= 4096; inp = W2; outp = w2T; Kd = FFd; Nd = DDm; }

    const int nx = Nd >> 5;
    const int ny = Kd >> 6;
    const int perz = nx * ny;
    const int z = b / perz;
    const int rem = b - z * perz;
    const int n0 = (rem % nx) * 32;
    const int k0 = (rem / nx) * 64;

    const float* inb = inp + (size_t)z * Kd * Nd;
    __half* outb = outp + (size_t)z * Nd * Kd;
    const int tx = tid & 31, ty = tid >> 5;

#pragma unroll
    for (int r = ty; r < 64; r += 8)
        t[r][tx] = inb[(size_t)(k0 + r) * Nd + n0 + tx];
    __syncthreads();

    const int c2 = tx * 2;
#pragma unroll
    for (int j = ty; j < 32; j += 8) {
        __half2 v = __floats2half2_rn(t[c2][j], t[c2 + 1][j]);
        *(__half2*)&outb[(size_t)(n0 + j) * Kd + k0 + c2] = v;
    }
}

// ---------------- fp16 tensor-core flash attention (3-buffer KV ring) -------
#define KROW 36
__global__ __launch_bounds__(256)
void fattn_k(const __half* __restrict__ Qg, const __half* __restrict__ Kg,
             const __half* __restrict__ Vt, __half* __restrict__ CTX)
{
    extern __shared__ uint32_t dsm[];
    uint32_t* sQ = dsm;
    uint32_t* sK = dsm + 128 * KROW;
    uint32_t* sV = dsm + 128 * KROW + 3 * 64 * KROW;

    const int b = blockIdx.z, h = blockIdx.y;
    const int q0 = blockIdx.x * 128;
    const int tid = threadIdx.x;
    const int warp = tid >> 5, lane = tid & 31;
    const int g = lane >> 2, t = lane & 3;

    const int krow = tid >> 2;
    const int keh  = (tid & 3) * 16;
    const int keb  = (tid & 3) * 8;

    {
        int row = tid >> 1, e0 = (tid & 1) * 32;
        const __half* src = Qg + (size_t)(b * SSQ + q0 + row) * DDm + h * DHH + e0;
        uint32_t dst = (uint32_t)__cvta_generic_to_shared(&sQ[row * KROW + (tid & 1) * 16]);
        CP_ASYNC16(dst,      src);
        CP_ASYNC16(dst + 16, src + 8);
        CP_ASYNC16(dst + 32, src + 16);
        CP_ASYNC16(dst + 48, src + 24);
    }
#define LOAD_TILE(buf, kv0) do { \
        uint32_t dk = (uint32_t)__cvta_generic_to_shared(&sK[(buf) * 64 * KROW + krow * KROW + keb]); \
        const __half* ks = Kg + (size_t)(b * SSQ + (kv0) + krow) * DDm + h * DHH + keh; \
        CP_ASYNC16(dk,      ks); \
        CP_ASYNC16(dk + 16, ks + 8); \
        uint32_t dv = (uint32_t)__cvta_generic_to_shared(&sV[(buf) * 64 * KROW + krow * KROW + keb]); \
        const __half* vs = Vt + (size_t)(h * DHH + krow) * BSr + (size_t)b * SSQ + (kv0) + keh; \
        CP_ASYNC16(dv,      vs); \
        CP_ASYNC16(dv + 16, vs + 8); \
    } while (0)

    LOAD_TILE(0, 0);
    CP_COMMIT();
    LOAD_TILE(1, 64);
    CP_COMMIT();

    CP_WAIT1();
    __syncthreads();

    uint32_t qa[4][4];
    {
        const uint32_t* sQw = sQ + (warp * 16) * KROW;
        const __half2 sc = __float2half2_rn(0.125f);
#pragma unroll
        for (int kc = 0; kc < 4; kc++) {
            int base = g * KROW + kc * 8 + t;
            qa[kc][0] = sQw[base];
            qa[kc][1] = sQw[base + 8 * KROW];
            qa[kc][2] = sQw[base + 4];
            qa[kc][3] = sQw[base + 8 * KROW + 4];
#pragma unroll
            for (int i = 0; i < 4; i++) {
                __half2 v = __hmul2(*(__half2*)&qa[kc][i], sc);
                qa[kc][i] = *(uint32_t*)&v;
            }
        }
    }

    float m0 = -1e30f, m1 = -1e30f, l0 = 0.0f, l1 = 0.0f;
    float o[8][4];
#pragma unroll
    for (int n = 0; n < 8; n++)
#pragma unroll
        for (int i = 0; i < 4; i++) o[n][i] = 0.0f;

    const int NIT = SSQ / 64;
    int cb3 = 0;
    for (int it = 0; it < NIT; it++) {
        CP_WAIT1();
        __syncthreads();

        if (it + 2 < NIT) {
            int lb = cb3 + 2; if (lb >= 3) lb -= 3;
            LOAD_TILE(lb, (it + 2) * 64);
        }
        CP_COMMIT();

        const uint32_t* kb = sK + cb3 * 64 * KROW;
        const uint32_t* vb = sV + cb3 * 64 * KROW;

        float acc[8][4];
#pragma unroll
        for (int n = 0; n < 8; n++)
#pragma unroll
            for (int i = 0; i < 4; i++) acc[n][i] = 0.0f;
#pragma unroll
        for (int kc = 0; kc < 4; kc++)
#pragma unroll
            for (int n = 0; n < 8; n++) {
                int base = (n * 8 + g) * KROW + kc * 8 + t;
                uint32_t b0 = kb[base];
                uint32_t b1 = kb[base + 4];
                MMA16816(acc[n], qa[kc], b0, b1);
            }

        float mx0 = -1e30f, mx1 = -1e30f;
#pragma unroll
        for (int n = 0; n < 8; n++) {
            mx0 = fmaxf(mx0, fmaxf(acc[n][0], acc[n][1]));
            mx1 = fmaxf(mx1, fmaxf(acc[n][2], acc[n][3]));
        }
        mx0 = fmaxf(mx0, __shfl_xor_sync(0xffffffffu, mx0, 1));
        mx0 = fmaxf(mx0, __shfl_xor_sync(0xffffffffu, mx0, 2));
        mx1 = fmaxf(mx1, __shfl_xor_sync(0xffffffffu, mx1, 1));
        mx1 = fmaxf(mx1, __shfl_xor_sync(0xffffffffu, mx1, 2));
        float nm0 = fmaxf(m0, mx0), nm1 = fmaxf(m1, mx1);
        float c0 = __expf(m0 - nm0), c1 = __expf(m1 - nm1);

        uint32_t pa[4][4];
        float s0 = 0.0f, s1 = 0.0f;
#pragma unroll
        for (int n = 0; n < 8; n++) {
            float p00 = __expf(acc[n][0] - nm0);
            float p01 = __expf(acc[n][1] - nm0);
            float p10 = __expf(acc[n][2] - nm1);
            float p11 = __expf(acc[n][3] - nm1);
            s0 += p00 + p01;
            s1 += p10 + p11;
            __half2 h0 = __floats2half2_rn(p00, p01);
            __half2 h1 = __floats2half2_rn(p10, p11);
            if (n & 1) {
                pa[n >> 1][2] = *(uint32_t*)&h0;
                pa[n >> 1][3] = *(uint32_t*)&h1;
            } else {
                pa[n >> 1][0] = *(uint32_t*)&h0;
                pa[n >> 1][1] = *(uint32_t*)&h1;
            }
        }
        s0 += __shfl_xor_sync(0xffffffffu, s0, 1);
        s0 += __shfl_xor_sync(0xffffffffu, s0, 2);
        s1 += __shfl_xor_sync(0xffffffffu, s1, 1);
        s1 += __shfl_xor_sync(0xffffffffu, s1, 2);
        l0 = l0 * c0 + s0;
        l1 = l1 * c1 + s1;
        m0 = nm0; m1 = nm1;
#pragma unroll
        for (int n = 0; n < 8; n++) {
            o[n][0] *= c0; o[n][1] *= c0;
            o[n][2] *= c1; o[n][3] *= c1;
        }

#pragma unroll
        for (int kc = 0; kc < 4; kc++)
#pragma unroll
            for (int n = 0; n < 8; n++) {
                int base = (n * 8 + g) * KROW + kc * 8 + t;
                uint32_t b0 = vb[base];
                uint32_t b1 = vb[base + 4];
                MMA16816(o[n], pa[kc], b0, b1);
            }

        if (++cb3 == 3) cb3 = 0;
    }

    float i0 = 1.0f / l0, i1 = 1.0f / l1;
    int r0 = b * SSQ + q0 + warp * 16 + g;
#pragma unroll
    for (int n = 0; n < 8; n++) {
        int col = h * DHH + n * 8 + t * 2;
        __half2 h0 = __floats2half2_rn(o[n][0] * i0, o[n][1] * i0);
        __half2 h1 = __floats2half2_rn(o[n][2] * i1, o[n][3] * i1);
        *(__half2*)&CTX[(size_t)r0 * DDm + col]       = h0;
        *(__half2*)&CTX[(size_t)(r0 + 8) * DDm + col] = h1;
    }
}

// ---------------- LayerNorm: warp-per-row, sync-free ------------------------
template<int OUT32, int OUT16>
__global__ __launch_bounds__(256)
void ln_k(const float* __restrict__ in, const float* __restrict__ w,
          const float* __restrict__ bb, float* __restrict__ out32,
          __half* __restrict__ out16)
{
    const int row  = blockIdx.x * 8 + (threadIdx.x >> 5);
    const int lane = threadIdx.x & 31;
    const float4* inr = (const float4*)(in + (size_t)row * DDm);

    float4 x[8];
    float s = 0.0f;
#pragma unroll
    for (int i = 0; i < 8; i++) {
        x[i] = inr[lane + i * 32];
        s += x[i].x + x[i].y + x[i].z + x[i].w;
    }
#pragma unroll
    for (int off = 16; off; off >>= 1) s += __shfl_xor_sync(0xffffffffu, s, off);
    float mean = s * (1.0f / DDm);

    float sq = 0.0f;
#pragma unroll
    for (int i = 0; i < 8; i++) {
        float d0 = x[i].x - mean, d1 = x[i].y - mean;
        float d2 = x[i].z - mean, d3 = x[i].w - mean;
        sq += d0 * d0 + d1 * d1 + d2 * d2 + d3 * d3;
    }
#pragma unroll
    for (int off = 16; off; off >>= 1) sq += __shfl_xor_sync(0xffffffffu, sq, off);
    float rs = rsqrtf(sq * (1.0f / DDm) + EPSLN);

    const float4* w4 = (const float4*)w;
    const float4* b4 = (const float4*)bb;
#pragma unroll
    for (int i = 0; i < 8; i++) {
        int c4 = lane + i * 32;
        float4 wv = w4[c4];
        float4 bv = b4[c4];
        float y0 = (x[i].x - mean) * rs * wv.x + bv.x;
        float y1 = (x[i].y - mean) * rs * wv.y + bv.y;
        float y2 = (x[i].z - mean) * rs * wv.z + bv.z;
        float y3 = (x[i].w - mean) * rs * wv.w + bv.w;
        if (OUT32)
            ((float4*)(out32 + (size_t)row * DDm))[c4] = make_float4(y0, y1, y2, y3);
        if (OUT16) {
            __half2* o2 = (__half2*)(out16 + (size_t)row * DDm) + c4 * 2;
            o2[0] = __floats2half2_rn(y0, y1);
            o2[1] = __floats2half2_rn(y2, y3);
        }
    }
}

// ---------------------------- launch ---------------------------------------
extern "C" void kernel_launch(void* const* d_in, const int* in_sizes, int n_in,
                              void* d_out, int out_size)
{
    const float* src   = (const float*)d_in[0];
    const float* Wq    = (const float*)d_in[1];
    const float* bq    = (const float*)d_in[2];
    const float* Wk    = (const float*)d_in[3];
    const float* bk    = (const float*)d_in[4];
    const float* Wv    = (const float*)d_in[5];
    const float* bv    = (const float*)d_in[6];
    const float* Wo    = (const float*)d_in[7];
    const float* bo    = (const float*)d_in[8];
    const float* ln1w  = (const float*)d_in[9];
    const float* ln1b  = (const float*)d_in[10];
    const float* W1    = (const float*)d_in[11];
    const float* b1    = (const float*)d_in[12];
    const float* W2    = (const float*)d_in[13];
    const float* b2    = (const float*)d_in[14];
    const float* ln2w  = (const float*)d_in[15];
    const float* ln2b  = (const float*)d_in[16];
    float* out = (float*)d_out;

    float *py1, *py2;
    __half *psrc16, *pq16, *pk16, *pvT16, *pctx16, *px16, *ph16;
    __half *pwqT, *pwkT, *pwvT, *pwoT, *pw1T, *pw2T;
    cudaGetSymbolAddress((void**)&py1,   g_y1);
    cudaGetSymbolAddress((void**)&py2,   g_y2);
    cudaGetSymbolAddress((void**)&psrc16, g_src16);
    cudaGetSymbolAddress((void**)&pq16,   g_q16);
    cudaGetSymbolAddress((void**)&pk16,   g_k16);
    cudaGetSymbolAddress((void**)&pvT16,  g_vT16);
    cudaGetSymbolAddress((void**)&pctx16, g_ctx16);
    cudaGetSymbolAddress((void**)&px16,   g_x16);
    cudaGetSymbolAddress((void**)&ph16,   g_h16);
    cudaGetSymbolAddress((void**)&pwqT,   g_wqT);
    cudaGetSymbolAddress((void**)&pwkT,   g_wkT);
    cudaGetSymbolAddress((void**)&pwvT,   g_wvT);
    cudaGetSymbolAddress((void**)&pwoT,   g_woT);
    cudaGetSymbolAddress((void**)&pw1T,   g_w1T);
    cudaGetSymbolAddress((void**)&pw2T,   g_w2T);

    const int ATTN_SMEM = (128 * KROW + 6 * 64 * KROW) * sizeof(uint32_t);
    cudaFuncSetAttribute(fattn_k, cudaFuncAttributeMaxDynamicSharedMemorySize, ATTN_SMEM);
    cudaFuncSetAttribute(hgemm_k<0,0,0,1,0>, cudaFuncAttributeMaxDynamicSharedMemorySize, HG_SMEM);
    cudaFuncSetAttribute(hgemm_k<0,0,0,0,1>, cudaFuncAttributeMaxDynamicSharedMemorySize, HG_SMEM);
    cudaFuncSetAttribute(hgemm_k<0,1,1,0,0>, cudaFuncAttributeMaxDynamicSharedMemorySize, HG_SMEM);
    cudaFuncSetAttribute(hgemm_k<1,0,0,1,0>, cudaFuncAttributeMaxDynamicSharedMemorySize, HG_SMEM);
    cudaFuncSetAttribute(hgemm_k<0,2,1,0,0>, cudaFuncAttributeMaxDynamicSharedMemorySize, HG_SMEM);

    dim3 thr(256);
    dim3 gD(DDm / 128, BSr / 128);     // (8, 64)
    dim3 gF(FFd / 128, BSr / 128);     // (32, 64)

    // ---- fused prep (one launch) ----
    prep_k<<<14336, thr>>>(src, psrc16, Wq, pwqT, Wk, pwkT, Wv, pwvT,
                           Wo, pwoT, W1, pw1T, W2, pw2T);

    // ---- QKV projections ----
    hgemm_k<0,0,0,1,0><<<gD, thr, HG_SMEM>>>(psrc16, pwqT, bq, nullptr, nullptr, pq16, BSr, DDm, DDm);
    hgemm_k<0,0,0,1,0><<<gD, thr, HG_SMEM>>>(psrc16, pwkT, bk, nullptr, nullptr, pk16, BSr, DDm, DDm);
    hgemm_k<0,0,0,0,1><<<gD, thr, HG_SMEM>>>(psrc16, pwvT, bv, nullptr, nullptr, pvT16, BSr, DDm, DDm);

    // ---- flash attention ----
    dim3 gAttn(SSQ / 128, HHn, BB);
    fattn_k<<<gAttn, thr, ATTN_SMEM>>>(pq16, pk16, pvT16, pctx16);

    // ---- output projection + residual, LN1 ----
    hgemm_k<0,1,1,0,0><<<gD, thr, HG_SMEM>>>(pctx16, pwoT, bo, src, py1, nullptr, BSr, DDm, DDm);
    ln_k<0,1><<<BSr / 8, thr>>>(py1, ln1w, ln1b, nullptr, px16);

    // ---- FFN ----
    hgemm_k<1,0,0,1,0><<<gF, thr, HG_SMEM>>>(px16, pw1T, b1, nullptr, nullptr, ph16, BSr, FFd, DDm);
    hgemm_k<0,2,1,0,0><<<gD, thr, HG_SMEM>>>(ph16, pw2T, b2, px16, py2, nullptr, BSr, DDm, FFd);
    ln_k<1,0><<<BSr / 8, thr>>>(py2, ln2w, ln2b, out, nullptr);
}

// round 15
// speedup vs baseline: 1.1072x; 1.1072x over previous
#include <cuda_runtime.h>
#include <cuda_fp16.h>
#include <cstddef>
#include <cstdint>

// Problem constants
#define BB  4
#define SSQ 2048
#define DDm 1024
#define HHn 16
#define DHH 64
#define FFd 4096
#define BSr (BB*SSQ)      // 8192 rows
#define EPSLN 1e-5f

// ---------------- scratch (device globals; allocation-free) ----------------
__device__ float g_y1 [BSr*DDm];
__device__ float g_y2 [BSr*DDm];

__device__ __half g_src16[BSr*DDm];
__device__ __half g_q16  [BSr*DDm];
__device__ __half g_k16  [BSr*DDm];
__device__ __half g_vT16 [(size_t)DDm*BSr];   // [n=h*64+dh][m=b*2048+s]
__device__ __half g_ctx16[BSr*DDm];
__device__ __half g_x16  [BSr*DDm];
__device__ __half g_h16  [(size_t)BSr*FFd];

__device__ __half g_wqT[DDm*DDm];
__device__ __half g_wkT[DDm*DDm];
__device__ __half g_wvT[DDm*DDm];
__device__ __half g_woT[DDm*DDm];
__device__ __half g_w1T[(size_t)DDm*FFd];
__device__ __half g_w2T[(size_t)DDm*FFd];

// ---------------- asm helpers -----------------------------------------------
#define CP_ASYNC16(dst, src) \
    asm volatile("cp.async.cg.shared.global [%0], [%1], 16;\n" :: "r"(dst), "l"(src))
#define CP_COMMIT() asm volatile("cp.async.commit_group;\n" ::)
#define CP_WAIT1()  asm volatile("cp.async.wait_group 1;\n" ::)

#define MMA16816(d, a, b0, b1) \
    asm volatile("mma.sync.aligned.m16n8k16.row.col.f32.f16.f16.f32 " \
        "{%0,%1,%2,%3},{%4,%5,%6,%7},{%8,%9},{%0,%1,%2,%3};\n" \
        : "+f"(d[0]), "+f"(d[1]), "+f"(d[2]), "+f"(d[3]) \
        : "r"(a[0]), "r"(a[1]), "r"(a[2]), "r"(a[3]), "r"(b0), "r"(b1))

__device__ __forceinline__ uint32_t smem_u32(const void* p) {
    uint32_t a;
    asm("{ .reg .u64 t; cvta.to.shared.u64 t, %1; cvt.u32.u64 %0, t; }" : "=r"(a) : "l"(p));
    return a;
}

// ---------------- fp16 HGEMM: C[M,N] = A16[M,K] @ Bt16[N,K]^T ---------------
// CTA 128x128, 8 warps of 32x64, BK=64 (half the barriers of BK=32),
// 3-stage cp.async ring (one sync/iter), scalar-LDS fragments.
// Rows padded to 72 halves (144 B, stride 36 b32 -> conflict-free frags).
// RES: 0 none, 1 f32 res, 2 fp16 res.  OUT16T: smem-staged transposed store.
#define ASTRB 144                 // bytes per smem row
#define STAGE_A 18432             // 128 * 144
#define STAGE   36864             // A + B
#define HG_SMEM (3 * STAGE)       // 110592
template<int RELU, int RES, int OUT32, int OUT16, int OUT16T>
__global__ __launch_bounds__(256)
void hgemm_k(const __half* __restrict__ A, const __half* __restrict__ Bt,
             const float* __restrict__ bias, const void* __restrict__ res,
             float* __restrict__ C32, __half* __restrict__ C16,
             int M, int N, int K)
{
    extern __shared__ __half smx[];
    const uint32_t sb = smem_u32(smx);

    const int tid  = threadIdx.x;
    const int warp = tid >> 5;
    const int lane = tid & 31;
    const int wm = (warp >> 1) * 32;
    const int wn = (warp & 1) * 64;
    const int bm = blockIdx.y * 128;
    const int bn = blockIdx.x * 128;

    // loaders: 2 threads per row, 32 halves (4 x 16B) each
    const int lrow  = tid >> 1;
    const int lcolh = (tid & 1) * 32;

    const __half* Ag = A  + (size_t)(bm + lrow) * K + lcolh;
    const __half* Bg = Bt + (size_t)(bn + lrow) * K + lcolh;

    const uint32_t saA = sb + lrow * ASTRB + (tid & 1) * 64;
    const uint32_t saB = saA + STAGE_A;

    float acc[2][8][4];
#pragma unroll
    for (int mt = 0; mt < 2; mt++)
#pragma unroll
        for (int nt = 0; nt < 8; nt++)
#pragma unroll
            for (int i = 0; i < 4; i++) acc[mt][nt][i] = 0.0f;

    const int r  = lane >> 2;
    const int cb = lane & 3;
    const int niter = K >> 6;

#define LD_STAGE(bo, k0) do { \
        CP_ASYNC16(saA + (bo),      Ag + (k0)); \
        CP_ASYNC16(saA + (bo) + 16, Ag + (k0) + 8); \
        CP_ASYNC16(saA + (bo) + 32, Ag + (k0) + 16); \
        CP_ASYNC16(saA + (bo) + 48, Ag + (k0) + 24); \
        CP_ASYNC16(saB + (bo),      Bg + (k0)); \
        CP_ASYNC16(saB + (bo) + 16, Bg + (k0) + 8); \
        CP_ASYNC16(saB + (bo) + 32, Bg + (k0) + 16); \
        CP_ASYNC16(saB + (bo) + 48, Bg + (k0) + 24); \
    } while (0)

    // prologue: stages 0,1
    LD_STAGE(0u, 0);
    CP_COMMIT();
    LD_STAGE((uint32_t)STAGE, 64);
    CP_COMMIT();

    int buf = 0;
    for (int kt = 0; kt < niter; kt++) {
        CP_WAIT1();
        __syncthreads();

        if (kt + 2 < niter) {
            int lb = buf + 2; if (lb >= 3) lb -= 3;
            LD_STAGE((uint32_t)lb * STAGE, (kt + 2) << 6);
        }
        CP_COMMIT();

        const uint32_t* Ab = (const uint32_t*)((const char*)smx + (size_t)buf * STAGE);
        const uint32_t* Bb = Ab + (STAGE_A / 4);
#pragma unroll
        for (int s = 0; s < 4; s++) {
            uint32_t af[2][4];
#pragma unroll
            for (int mt = 0; mt < 2; mt++) {
                int base = (wm + mt * 16 + r) * 36 + s * 8 + cb;
                af[mt][0] = Ab[base];
                af[mt][1] = Ab[base + 288];       // +8 rows
                af[mt][2] = Ab[base + 4];         // k+8
                af[mt][3] = Ab[base + 292];
            }
#pragma unroll
            for (int nt = 0; nt < 8; nt++) {
                int nb = (wn + nt * 8 + r) * 36 + s * 8 + cb;
                uint32_t b0 = Bb[nb];
                uint32_t b1 = Bb[nb + 4];
                MMA16816(acc[0][nt], af[0], b0, b1);
                MMA16816(acc[1][nt], af[1], b0, b1);
            }
        }
        if (++buf == 3) buf = 0;
    }

    const float* resf = (const float*)res;
    const __half* resh = (const __half*)res;

    if (OUT16T) {
        __syncthreads();
        __half* st = smx;
#pragma unroll
        for (int mt = 0; mt < 2; mt++) {
#pragma unroll
            for (int hh = 0; hh < 2; hh++) {
                int rl = wm + mt * 16 + r + hh * 8;
#pragma unroll
                for (int nt = 0; nt < 8; nt++) {
                    int cl = wn + nt * 8 + cb * 2;
                    float v0 = acc[mt][nt][hh * 2 + 0] + bias[bn + cl];
                    float v1 = acc[mt][nt][hh * 2 + 1] + bias[bn + cl + 1];
                    st[cl * 136 + rl]       = __float2half_rn(v0);
                    st[(cl + 1) * 136 + rl] = __float2half_rn(v1);
                }
            }
        }
        __syncthreads();
        const int c16 = tid >> 4;
        const int rr  = (tid & 15) * 8;
#pragma unroll
        for (int p = 0; p < 8; p++) {
            int c = c16 + p * 16;
            *(float4*)&C16[(size_t)(bn + c) * M + bm + rr] =
                *(const float4*)&st[c * 136 + rr];
        }
        return;
    }

#pragma unroll
    for (int mt = 0; mt < 2; mt++) {
#pragma unroll
        for (int hh = 0; hh < 2; hh++) {
            int row = bm + wm + mt * 16 + r + hh * 8;
#pragma unroll
            for (int nt = 0; nt < 8; nt++) {
                int col = bn + wn + nt * 8 + cb * 2;
                float v0 = acc[mt][nt][hh * 2 + 0] + bias[col];
                float v1 = acc[mt][nt][hh * 2 + 1] + bias[col + 1];
                if (RES == 1) {
                    float2 rv = *(const float2*)&resf[(size_t)row * N + col];
                    v0 += rv.x; v1 += rv.y;
                }
                if (RES == 2) {
                    __half2 rh = *(const __half2*)&resh[(size_t)row * N + col];
                    float2 rv = __half22float2(rh);
                    v0 += rv.x; v1 += rv.y;
                }
                if (RELU) { v0 = fmaxf(v0, 0.0f); v1 = fmaxf(v1, 0.0f); }
                if (OUT32)
                    *(float2*)&C32[(size_t)row * N + col] = make_float2(v0, v1);
                if (OUT16)
                    *(__half2*)&C16[(size_t)row * N + col] = __floats2half2_rn(v0, v1);
            }
        }
    }
}

// ---------------- fused prep: src conv + all 6 weight transposes ------------
__global__ __launch_bounds__(256)
void prep_k(const float* __restrict__ src, __half* __restrict__ src16,
            const float* __restrict__ Wq, __half* __restrict__ wqT,
            const float* __restrict__ Wk, __half* __restrict__ wkT,
            const float* __restrict__ Wv, __half* __restrict__ wvT,
            const float* __restrict__ Wo, __half* __restrict__ woT,
            const float* __restrict__ W1, __half* __restrict__ w1T,
            const float* __restrict__ W2, __half* __restrict__ w2T)
{
    __shared__ float t[64][33];
    const int tid = threadIdx.x;
    int b = blockIdx.x;

    if (b < 8192) {
        int i = b * 256 + tid;
        float4 v = ((const float4*)src)[i];
        __half2* o = (__half2*)src16;
        o[i * 2 + 0] = __floats2half2_rn(v.x, v.y);
        o[i * 2 + 1] = __floats2half2_rn(v.z, v.w);
        return;
    }
    b -= 8192;

    const float* inp; __half* outp; int Kd, Nd;
    if (b < 512)            { inp = Wq; outp = wqT; Kd = DDm; Nd = DHH; }
    else if (b < 1024)      { b -= 512;  inp = Wk; outp = wkT; Kd = DDm; Nd = DHH; }
    else if (b < 1536)      { b -= 1024; inp = Wv; outp = wvT; Kd = DDm; Nd = DHH; }
    else if (b < 2048)      { b -= 1536; inp = Wo; outp = woT; Kd = DDm; Nd = DDm; }
    else if (b < 4096)      { b -= 2048; inp = W1; outp = w1T; Kd = DDm; Nd = FFd; }
    else                    { b -= 4096; inp = W2; outp = w2T; Kd = FFd; Nd = DDm; }

    const int nx = Nd >> 5;
    const int ny = Kd >> 6;
    const int perz = nx * ny;
    const int z = b / perz;
    const int rem = b - z * perz;
    const int n0 = (rem % nx) * 32;
    const int k0 = (rem / nx) * 64;

    const float* inb = inp + (size_t)z * Kd * Nd;
    __half* outb = outp + (size_t)z * Nd * Kd;
    const int tx = tid & 31, ty = tid >> 5;

#pragma unroll
    for (int r = ty; r < 64; r += 8)
        t[r][tx] = inb[(size_t)(k0 + r) * Nd + n0 + tx];
    __syncthreads();

    const int c2 = tx * 2;
#pragma unroll
    for (int j = ty; j < 32; j += 8) {
        __half2 v = __floats2half2_rn(t[c2][j], t[c2 + 1][j]);
        *(__half2*)&outb[(size_t)(n0 + j) * Kd + k0 + c2] = v;
    }
}

// ---------------- fp16 tensor-core flash attention (3-buffer KV ring) -------
#define KROW 36
__global__ __launch_bounds__(256)
void fattn_k(const __half* __restrict__ Qg, const __half* __restrict__ Kg,
             const __half* __restrict__ Vt, __half* __restrict__ CTX)
{
    extern __shared__ uint32_t dsm[];
    uint32_t* sQ = dsm;
    uint32_t* sK = dsm + 128 * KROW;
    uint32_t* sV = dsm + 128 * KROW + 3 * 64 * KROW;

    const int b = blockIdx.z, h = blockIdx.y;
    const int q0 = blockIdx.x * 128;
    const int tid = threadIdx.x;
    const int warp = tid >> 5, lane = tid & 31;
    const int g = lane >> 2, t = lane & 3;

    const int krow = tid >> 2;
    const int keh  = (tid & 3) * 16;
    const int keb  = (tid & 3) * 8;

    {
        int row = tid >> 1, e0 = (tid & 1) * 32;
        const __half* src = Qg + (size_t)(b * SSQ + q0 + row) * DDm + h * DHH + e0;
        uint32_t dst = (uint32_t)__cvta_generic_to_shared(&sQ[row * KROW + (tid & 1) * 16]);
        CP_ASYNC16(dst,      src);
        CP_ASYNC16(dst + 16, src + 8);
        CP_ASYNC16(dst + 32, src + 16);
        CP_ASYNC16(dst + 48, src + 24);
    }
#define LOAD_TILE(buf, kv0) do { \
        uint32_t dk = (uint32_t)__cvta_generic_to_shared(&sK[(buf) * 64 * KROW + krow * KROW + keb]); \
        const __half* ks = Kg + (size_t)(b * SSQ + (kv0) + krow) * DDm + h * DHH + keh; \
        CP_ASYNC16(dk,      ks); \
        CP_ASYNC16(dk + 16, ks + 8); \
        uint32_t dv = (uint32_t)__cvta_generic_to_shared(&sV[(buf) * 64 * KROW + krow * KROW + keb]); \
        const __half* vs = Vt + (size_t)(h * DHH + krow) * BSr + (size_t)b * SSQ + (kv0) + keh; \
        CP_ASYNC16(dv,      vs); \
        CP_ASYNC16(dv + 16, vs + 8); \
    } while (0)

    LOAD_TILE(0, 0);
    CP_COMMIT();
    LOAD_TILE(1, 64);
    CP_COMMIT();

    CP_WAIT1();
    __syncthreads();

    uint32_t qa[4][4];
    {
        const uint32_t* sQw = sQ + (warp * 16) * KROW;
        const __half2 sc = __float2half2_rn(0.125f);
#pragma unroll
        for (int kc = 0; kc < 4; kc++) {
            int base = g * KROW + kc * 8 + t;
            qa[kc][0] = sQw[base];
            qa[kc][1] = sQw[base + 8 * KROW];
            qa[kc][2] = sQw[base + 4];
            qa[kc][3] = sQw[base + 8 * KROW + 4];
#pragma unroll
            for (int i = 0; i < 4; i++) {
                __half2 v = __hmul2(*(__half2*)&qa[kc][i], sc);
                qa[kc][i] = *(uint32_t*)&v;
            }
        }
    }

    float m0 = -1e30f, m1 = -1e30f, l0 = 0.0f, l1 = 0.0f;
    float o[8][4];
#pragma unroll
    for (int n = 0; n < 8; n++)
#pragma unroll
        for (int i = 0; i < 4; i++) o[n][i] = 0.0f;

    const int NIT = SSQ / 64;
    int cb3 = 0;
    for (int it = 0; it < NIT; it++) {
        CP_WAIT1();
        __syncthreads();

        if (it + 2 < NIT) {
            int lb = cb3 + 2; if (lb >= 3) lb -= 3;
            LOAD_TILE(lb, (it + 2) * 64);
        }
        CP_COMMIT();

        const uint32_t* kb = sK + cb3 * 64 * KROW;
        const uint32_t* vb = sV + cb3 * 64 * KROW;

        float acc[8][4];
#pragma unroll
        for (int n = 0; n < 8; n++)
#pragma unroll
            for (int i = 0; i < 4; i++) acc[n][i] = 0.0f;
#pragma unroll
        for (int kc = 0; kc < 4; kc++)
#pragma unroll
            for (int n = 0; n < 8; n++) {
                int base = (n * 8 + g) * KROW + kc * 8 + t;
                uint32_t b0 = kb[base];
                uint32_t b1 = kb[base + 4];
                MMA16816(acc[n], qa[kc], b0, b1);
            }

        float mx0 = -1e30f, mx1 = -1e30f;
#pragma unroll
        for (int n = 0; n < 8; n++) {
            mx0 = fmaxf(mx0, fmaxf(acc[n][0], acc[n][1]));
            mx1 = fmaxf(mx1, fmaxf(acc[n][2], acc[n][3]));
        }
        mx0 = fmaxf(mx0, __shfl_xor_sync(0xffffffffu, mx0, 1));
        mx0 = fmaxf(mx0, __shfl_xor_sync(0xffffffffu, mx0, 2));
        mx1 = fmaxf(mx1, __shfl_xor_sync(0xffffffffu, mx1, 1));
        mx1 = fmaxf(mx1, __shfl_xor_sync(0xffffffffu, mx1, 2));
        float nm0 = fmaxf(m0, mx0), nm1 = fmaxf(m1, mx1);
        float c0 = __expf(m0 - nm0), c1 = __expf(m1 - nm1);

        uint32_t pa[4][4];
        float s0 = 0.0f, s1 = 0.0f;
#pragma unroll
        for (int n = 0; n < 8; n++) {
            float p00 = __expf(acc[n][0] - nm0);
            float p01 = __expf(acc[n][1] - nm0);
            float p10 = __expf(acc[n][2] - nm1);
            float p11 = __expf(acc[n][3] - nm1);
            s0 += p00 + p01;
            s1 += p10 + p11;
            __half2 h0 = __floats2half2_rn(p00, p01);
            __half2 h1 = __floats2half2_rn(p10, p11);
            if (n & 1) {
                pa[n >> 1][2] = *(uint32_t*)&h0;
                pa[n >> 1][3] = *(uint32_t*)&h1;
            } else {
                pa[n >> 1][0] = *(uint32_t*)&h0;
                pa[n >> 1][1] = *(uint32_t*)&h1;
            }
        }
        s0 += __shfl_xor_sync(0xffffffffu, s0, 1);
        s0 += __shfl_xor_sync(0xffffffffu, s0, 2);
        s1 += __shfl_xor_sync(0xffffffffu, s1, 1);
        s1 += __shfl_xor_sync(0xffffffffu, s1, 2);
        l0 = l0 * c0 + s0;
        l1 = l1 * c1 + s1;
        m0 = nm0; m1 = nm1;
#pragma unroll
        for (int n = 0; n < 8; n++) {
            o[n][0] *= c0; o[n][1] *= c0;
            o[n][2] *= c1; o[n][3] *= c1;
        }

#pragma unroll
        for (int kc = 0; kc < 4; kc++)
#pragma unroll
            for (int n = 0; n < 8; n++) {
                int base = (n * 8 + g) * KROW + kc * 8 + t;
                uint32_t b0 = vb[base];
                uint32_t b1 = vb[base + 4];
                MMA16816(o[n], pa[kc], b0, b1);
            }

        if (++cb3 == 3) cb3 = 0;
    }

    float i0 = 1.0f / l0, i1 = 1.0f / l1;
    int r0 = b * SSQ + q0 + warp * 16 + g;
#pragma unroll
    for (int n = 0; n < 8; n++) {
        int col = h * DHH + n * 8 + t * 2;
        __half2 h0 = __floats2half2_rn(o[n][0] * i0, o[n][1] * i0);
        __half2 h1 = __floats2half2_rn(o[n][2] * i1, o[n][3] * i1);
        *(__half2*)&CTX[(size_t)r0 * DDm + col]       = h0;
        *(__half2*)&CTX[(size_t)(r0 + 8) * DDm + col] = h1;
    }
}

// ---------------- LayerNorm: warp-per-row, sync-free ------------------------
template<int OUT32, int OUT16>
__global__ __launch_bounds__(256)
void ln_k(const float* __restrict__ in, const float* __restrict__ w,
          const float* __restrict__ bb, float* __restrict__ out32,
          __half* __restrict__ out16)
{
    const int row  = blockIdx.x * 8 + (threadIdx.x >> 5);
    const int lane = threadIdx.x & 31;
    const float4* inr = (const float4*)(in + (size_t)row * DDm);

    float4 x[8];
    float s = 0.0f;
#pragma unroll
    for (int i = 0; i < 8; i++) {
        x[i] = inr[lane + i * 32];
        s += x[i].x + x[i].y + x[i].z + x[i].w;
    }
#pragma unroll
    for (int off = 16; off; off >>= 1) s += __shfl_xor_sync(0xffffffffu, s, off);
    float mean = s * (1.0f / DDm);

    float sq = 0.0f;
#pragma unroll
    for (int i = 0; i < 8; i++) {
        float d0 = x[i].x - mean, d1 = x[i].y - mean;
        float d2 = x[i].z - mean, d3 = x[i].w - mean;
        sq += d0 * d0 + d1 * d1 + d2 * d2 + d3 * d3;
    }
#pragma unroll
    for (int off = 16; off; off >>= 1) sq += __shfl_xor_sync(0xffffffffu, sq, off);
    float rs = rsqrtf(sq * (1.0f / DDm) + EPSLN);

    const float4* w4 = (const float4*)w;
    const float4* b4 = (const float4*)bb;
#pragma unroll
    for (int i = 0; i < 8; i++) {
        int c4 = lane + i * 32;
        float4 wv = w4[c4];
        float4 bv = b4[c4];
        float y0 = (x[i].x - mean) * rs * wv.x + bv.x;
        float y1 = (x[i].y - mean) * rs * wv.y + bv.y;
        float y2 = (x[i].z - mean) * rs * wv.z + bv.z;
        float y3 = (x[i].w - mean) * rs * wv.w + bv.w;
        if (OUT32)
            ((float4*)(out32 + (size_t)row * DDm))[c4] = make_float4(y0, y1, y2, y3);
        if (OUT16) {
            __half2* o2 = (__half2*)(out16 + (size_t)row * DDm) + c4 * 2;
            o2[0] = __floats2half2_rn(y0, y1);
            o2[1] = __floats2half2_rn(y2, y3);
        }
    }
}

// ---------------------------- launch ---------------------------------------
extern "C" void kernel_launch(void* const* d_in, const int* in_sizes, int n_in,
                              void* d_out, int out_size)
{
    const float* src   = (const float*)d_in[0];
    const float* Wq    = (const float*)d_in[1];
    const float* bq    = (const float*)d_in[2];
    const float* Wk    = (const float*)d_in[3];
    const float* bk    = (const float*)d_in[4];
    const float* Wv    = (const float*)d_in[5];
    const float* bv    = (const float*)d_in[6];
    const float* Wo    = (const float*)d_in[7];
    const float* bo    = (const float*)d_in[8];
    const float* ln1w  = (const float*)d_in[9];
    const float* ln1b  = (const float*)d_in[10];
    const float* W1    = (const float*)d_in[11];
    const float* b1    = (const float*)d_in[12];
    const float* W2    = (const float*)d_in[13];
    const float* b2    = (const float*)d_in[14];
    const float* ln2w  = (const float*)d_in[15];
    const float* ln2b  = (const float*)d_in[16];
    float* out = (float*)d_out;

    float *py1, *py2;
    __half *psrc16, *pq16, *pk16, *pvT16, *pctx16, *px16, *ph16;
    __half *pwqT, *pwkT, *pwvT, *pwoT, *pw1T, *pw2T;
    cudaGetSymbolAddress((void**)&py1,   g_y1);
    cudaGetSymbolAddress((void**)&py2,   g_y2);
    cudaGetSymbolAddress((void**)&psrc16, g_src16);
    cudaGetSymbolAddress((void**)&pq16,   g_q16);
    cudaGetSymbolAddress((void**)&pk16,   g_k16);
    cudaGetSymbolAddress((void**)&pvT16,  g_vT16);
    cudaGetSymbolAddress((void**)&pctx16, g_ctx16);
    cudaGetSymbolAddress((void**)&px16,   g_x16);
    cudaGetSymbolAddress((void**)&ph16,   g_h16);
    cudaGetSymbolAddress((void**)&pwqT,   g_wqT);
    cudaGetSymbolAddress((void**)&pwkT,   g_wkT);
    cudaGetSymbolAddress((void**)&pwvT,   g_wvT);
    cudaGetSymbolAddress((void**)&pwoT,   g_woT);
    cudaGetSymbolAddress((void**)&pw1T,   g_w1T);
    cudaGetSymbolAddress((void**)&pw2T,   g_w2T);

    const int ATTN_SMEM = (128 * KROW + 6 * 64 * KROW) * sizeof(uint32_t);
    cudaFuncSetAttribute(fattn_k, cudaFuncAttributeMaxDynamicSharedMemorySize, ATTN_SMEM);
    cudaFuncSetAttribute(hgemm_k<0,0,0,1,0>, cudaFuncAttributeMaxDynamicSharedMemorySize, HG_SMEM);
    cudaFuncSetAttribute(hgemm_k<0,0,0,0,1>, cudaFuncAttributeMaxDynamicSharedMemorySize, HG_SMEM);
    cudaFuncSetAttribute(hgemm_k<0,1,1,0,0>, cudaFuncAttributeMaxDynamicSharedMemorySize, HG_SMEM);
    cudaFuncSetAttribute(hgemm_k<1,0,0,1,0>, cudaFuncAttributeMaxDynamicSharedMemorySize, HG_SMEM);
    cudaFuncSetAttribute(hgemm_k<0,2,1,0,0>, cudaFuncAttributeMaxDynamicSharedMemorySize, HG_SMEM);

    dim3 thr(256);
    dim3 gD(DDm / 128, BSr / 128);     // (8, 64)
    dim3 gF(FFd / 128, BSr / 128);     // (32, 64)

    // ---- fused prep (one launch) ----
    prep_k<<<14336, thr>>>(src, psrc16, Wq, pwqT, Wk, pwkT, Wv, pwvT,
                           Wo, pwoT, W1, pw1T, W2, pw2T);

    // ---- QKV projections ----
    hgemm_k<0,0,0,1,0><<<gD, thr, HG_SMEM>>>(psrc16, pwqT, bq, nullptr, nullptr, pq16, BSr, DDm, DDm);
    hgemm_k<0,0,0,1,0><<<gD, thr, HG_SMEM>>>(psrc16, pwkT, bk, nullptr, nullptr, pk16, BSr, DDm, DDm);
    hgemm_k<0,0,0,0,1><<<gD, thr, HG_SMEM>>>(psrc16, pwvT, bv, nullptr, nullptr, pvT16, BSr, DDm, DDm);

    // ---- flash attention ----
    dim3 gAttn(SSQ / 128, HHn, BB);
    fattn_k<<<gAttn, thr, ATTN_SMEM>>>(pq16, pk16, pvT16, pctx16);

    // ---- output projection + residual, LN1 ----
    hgemm_k<0,1,1,0,0><<<gD, thr, HG_SMEM>>>(pctx16, pwoT, bo, src, py1, nullptr, BSr, DDm, DDm);
    ln_k<0,1><<<BSr / 8, thr>>>(py1, ln1w, ln1b, nullptr, px16);

    // ---- FFN ----
    hgemm_k<1,0,0,1,0><<<gF, thr, HG_SMEM>>>(px16, pw1T, b1, nullptr, nullptr, ph16, BSr, FFd, DDm);
    hgemm_k<0,2,1,0,0><<<gD, thr, HG_SMEM>>>(ph16, pw2T, b2, px16, py2, nullptr, BSr, DDm, FFd);
    ln_k<1,0><<<BSr / 8, thr>>>(py2, ln2w, ln2b, out, nullptr);
}

// round 16
// speedup vs baseline: 1.2151x; 1.0975x over previous
#include <cuda_runtime.h>
#include <cuda_fp16.h>
#include <cstddef>
#include <cstdint>

// Problem constants
#define BB  4
#define SSQ 2048
#define DDm 1024
#define HHn 16
#define DHH 64
#define FFd 4096
#define BSr (BB*SSQ)      // 8192 rows
#define EPSLN 1e-5f

// ---------------- scratch (device globals; allocation-free) ----------------
__device__ float g_y1 [BSr*DDm];
__device__ float g_y2 [BSr*DDm];

__device__ __half g_src16[BSr*DDm];
__device__ __half g_q16  [BSr*DDm];
__device__ __half g_k16  [BSr*DDm];
__device__ __half g_vT16 [(size_t)DDm*BSr];   // [n=h*64+dh][m=b*2048+s]
__device__ __half g_ctx16[BSr*DDm];
__device__ __half g_x16  [BSr*DDm];
__device__ __half g_h16  [(size_t)BSr*FFd];

__device__ __half g_wqT[DDm*DDm];
__device__ __half g_wkT[DDm*DDm];
__device__ __half g_wvT[DDm*DDm];
__device__ __half g_woT[DDm*DDm];
__device__ __half g_w1T[(size_t)DDm*FFd];
__device__ __half g_w2T[(size_t)DDm*FFd];

// ---------------- asm helpers -----------------------------------------------
#define CP_ASYNC16(dst, src) \
    asm volatile("cp.async.cg.shared.global [%0], [%1], 16;\n" :: "r"(dst), "l"(src))
#define CP_COMMIT() asm volatile("cp.async.commit_group;\n" ::)
#define CP_WAIT1()  asm volatile("cp.async.wait_group 1;\n" ::)

#define MMA16816(d, a, b0, b1) \
    asm volatile("mma.sync.aligned.m16n8k16.row.col.f32.f16.f16.f32 " \
        "{%0,%1,%2,%3},{%4,%5,%6,%7},{%8,%9},{%0,%1,%2,%3};\n" \
        : "+f"(d[0]), "+f"(d[1]), "+f"(d[2]), "+f"(d[3]) \
        : "r"(a[0]), "r"(a[1]), "r"(a[2]), "r"(a[3]), "r"(b0), "r"(b1))

__device__ __forceinline__ uint32_t smem_u32(const void* p) {
    uint32_t a;
    asm("{ .reg .u64 t; cvta.to.shared.u64 t, %1; cvt.u32.u64 %0, t; }" : "=r"(a) : "l"(p));
    return a;
}

// ======= shared mainloop (R13 config: BK=32, SROW=40, 3-stage ring) =========
#define SROW 40
#define HBUF 20480
#define HG_SMEM (3 * HBUF)

// Computes the 128x128 tile accumulators. smx = dynamic smem base.
__device__ __forceinline__ void hg_mainloop(
    const __half* __restrict__ A, const __half* __restrict__ Bt,
    int bm, int bn, int K, __half* smx, float acc[2][8][4])
{
    const uint32_t sb = smem_u32(smx);
    const int tid  = threadIdx.x;
    const int warp = tid >> 5;
    const int lane = tid & 31;
    const int wm = (warp >> 1) * 32;
    const int wn = (warp & 1) * 64;

    const int lrow  = tid >> 1;
    const int lcolh = (tid & 1) * 16;

    const __half* Ag = A  + (size_t)(bm + lrow) * K + lcolh;
    const __half* Bg = Bt + (size_t)(bn + lrow) * K + lcolh;

    const uint32_t saA = sb + lrow * 80 + (tid & 1) * 32;
    const uint32_t saB = saA + 10240;

#pragma unroll
    for (int mt = 0; mt < 2; mt++)
#pragma unroll
        for (int nt = 0; nt < 8; nt++)
#pragma unroll
            for (int i = 0; i < 4; i++) acc[mt][nt][i] = 0.0f;

    const int r  = lane >> 2;
    const int cb = lane & 3;
    const int niter = K >> 5;

#pragma unroll
    for (int ch = 0; ch < 2; ch++) {
        uint32_t bo = (uint32_t)ch * HBUF;
        int k0 = ch << 5;
        CP_ASYNC16(saA + bo,      Ag + k0);
        CP_ASYNC16(saA + bo + 16, Ag + k0 + 8);
        CP_ASYNC16(saB + bo,      Bg + k0);
        CP_ASYNC16(saB + bo + 16, Bg + k0 + 8);
        CP_COMMIT();
    }

    int buf = 0;
    for (int kt = 0; kt < niter; kt++) {
        CP_WAIT1();
        __syncthreads();

        if (kt + 2 < niter) {
            int lb = buf + 2; if (lb >= 3) lb -= 3;
            uint32_t bo = (uint32_t)lb * HBUF;
            int k0 = (kt + 2) << 5;
            CP_ASYNC16(saA + bo,      Ag + k0);
            CP_ASYNC16(saA + bo + 16, Ag + k0 + 8);
            CP_ASYNC16(saB + bo,      Bg + k0);
            CP_ASYNC16(saB + bo + 16, Bg + k0 + 8);
        }
        CP_COMMIT();

        const uint32_t* Ab = (const uint32_t*)(smx + (size_t)buf * (HBUF / 2));
        const uint32_t* Bb = Ab + 2560;
#pragma unroll
        for (int s = 0; s < 2; s++) {
            uint32_t af[2][4];
#pragma unroll
            for (int mt = 0; mt < 2; mt++) {
                int base = (wm + mt * 16 + r) * 20 + s * 8 + cb;
                af[mt][0] = Ab[base];
                af[mt][1] = Ab[base + 160];
                af[mt][2] = Ab[base + 4];
                af[mt][3] = Ab[base + 164];
            }
#pragma unroll
            for (int nt = 0; nt < 8; nt++) {
                int nb = (wn + nt * 8 + r) * 20 + s * 8 + cb;
                uint32_t b0 = Bb[nb];
                uint32_t b1 = Bb[nb + 4];
                MMA16816(acc[0][nt], af[0], b0, b1);
                MMA16816(acc[1][nt], af[1], b0, b1);
            }
        }
        if (++buf == 3) buf = 0;
    }
}

// epilogue: transposed fp16 store via smem staging (coalesced)
__device__ __forceinline__ void hg_store_t(
    float acc[2][8][4], const float* __restrict__ bias,
    __half* __restrict__ C16, int bm, int bn, int M, __half* smx)
{
    const int tid  = threadIdx.x;
    const int warp = tid >> 5;
    const int lane = tid & 31;
    const int wm = (warp >> 1) * 32;
    const int wn = (warp & 1) * 64;
    const int r  = lane >> 2;
    const int cb = lane & 3;

    __syncthreads();
    __half* st = smx;
#pragma unroll
    for (int mt = 0; mt < 2; mt++) {
#pragma unroll
        for (int hh = 0; hh < 2; hh++) {
            int rl = wm + mt * 16 + r + hh * 8;
#pragma unroll
            for (int nt = 0; nt < 8; nt++) {
                int cl = wn + nt * 8 + cb * 2;
                float v0 = acc[mt][nt][hh * 2 + 0] + bias[bn + cl];
                float v1 = acc[mt][nt][hh * 2 + 1] + bias[bn + cl + 1];
                st[cl * 136 + rl]       = __float2half_rn(v0);
                st[(cl + 1) * 136 + rl] = __float2half_rn(v1);
            }
        }
    }
    __syncthreads();
    const int c16 = tid >> 4;
    const int rr  = (tid & 15) * 8;
#pragma unroll
    for (int p = 0; p < 8; p++) {
        int c = c16 + p * 16;
        *(float4*)&C16[(size_t)(bn + c) * M + bm + rr] =
            *(const float4*)&st[c * 136 + rr];
    }
}

// ---------------- merged QKV GEMM: z selects {q,k,v} ------------------------
__global__ __launch_bounds__(256)
void hgemm_qkv_k(const __half* __restrict__ A,
                 const __half* __restrict__ BtQ, const __half* __restrict__ BtK,
                 const __half* __restrict__ BtV,
                 const float* __restrict__ bq, const float* __restrict__ bk,
                 const float* __restrict__ bv,
                 __half* __restrict__ Cq, __half* __restrict__ Ck,
                 __half* __restrict__ CvT)
{
    extern __shared__ __half smx[];
    const int z = blockIdx.z;
    const int bm = blockIdx.y * 128;
    const int bn = blockIdx.x * 128;

    const __half* Bt = (z == 0) ? BtQ : (z == 1) ? BtK : BtV;
    const float* bias = (z == 0) ? bq : (z == 1) ? bk : bv;

    float acc[2][8][4];
    hg_mainloop(A, Bt, bm, bn, DDm, smx, acc);

    if (z == 2) {
        hg_store_t(acc, bias, CvT, bm, bn, BSr, smx);
        return;
    }
    __half* C16 = (z == 0) ? Cq : Ck;
    const int tid  = threadIdx.x;
    const int warp = tid >> 5;
    const int lane = tid & 31;
    const int wm = (warp >> 1) * 32;
    const int wn = (warp & 1) * 64;
    const int r  = lane >> 2;
    const int cb = lane & 3;
#pragma unroll
    for (int mt = 0; mt < 2; mt++) {
#pragma unroll
        for (int hh = 0; hh < 2; hh++) {
            int row = bm + wm + mt * 16 + r + hh * 8;
#pragma unroll
            for (int nt = 0; nt < 8; nt++) {
                int col = bn + wn + nt * 8 + cb * 2;
                float v0 = acc[mt][nt][hh * 2 + 0] + bias[col];
                float v1 = acc[mt][nt][hh * 2 + 1] + bias[col + 1];
                *(__half2*)&C16[(size_t)row * DDm + col] = __floats2half2_rn(v0, v1);
            }
        }
    }
}

// ---------------- generic HGEMM (Wo / W1 / W2 paths) ------------------------
// RES: 0 none, 1 f32 res, 2 fp16 res.
template<int RELU, int RES, int OUT32, int OUT16>
__global__ __launch_bounds__(256)
void hgemm_k(const __half* __restrict__ A, const __half* __restrict__ Bt,
             const float* __restrict__ bias, const void* __restrict__ res,
             float* __restrict__ C32, __half* __restrict__ C16,
             int M, int N, int K)
{
    extern __shared__ __half smx[];
    const int bm = blockIdx.y * 128;
    const int bn = blockIdx.x * 128;

    float acc[2][8][4];
    hg_mainloop(A, Bt, bm, bn, K, smx, acc);

    const float* resf = (const float*)res;
    const __half* resh = (const __half*)res;
    const int tid  = threadIdx.x;
    const int warp = tid >> 5;
    const int lane = tid & 31;
    const int wm = (warp >> 1) * 32;
    const int wn = (warp & 1) * 64;
    const int r  = lane >> 2;
    const int cb = lane & 3;

#pragma unroll
    for (int mt = 0; mt < 2; mt++) {
#pragma unroll
        for (int hh = 0; hh < 2; hh++) {
            int row = bm + wm + mt * 16 + r + hh * 8;
#pragma unroll
            for (int nt = 0; nt < 8; nt++) {
                int col = bn + wn + nt * 8 + cb * 2;
                float v0 = acc[mt][nt][hh * 2 + 0] + bias[col];
                float v1 = acc[mt][nt][hh * 2 + 1] + bias[col + 1];
                if (RES == 1) {
                    float2 rv = *(const float2*)&resf[(size_t)row * N + col];
                    v0 += rv.x; v1 += rv.y;
                }
                if (RES == 2) {
                    __half2 rh = *(const __half2*)&resh[(size_t)row * N + col];
                    float2 rv = __half22float2(rh);
                    v0 += rv.x; v1 += rv.y;
                }
                if (RELU) { v0 = fmaxf(v0, 0.0f); v1 = fmaxf(v1, 0.0f); }
                if (OUT32)
                    *(float2*)&C32[(size_t)row * N + col] = make_float2(v0, v1);
                if (OUT16)
                    *(__half2*)&C16[(size_t)row * N + col] = __floats2half2_rn(v0, v1);
            }
        }
    }
}

// ---------------- fused prep: src conv + all 6 weight transposes ------------
__global__ __launch_bounds__(256)
void prep_k(const float* __restrict__ src, __half* __restrict__ src16,
            const float* __restrict__ Wq, __half* __restrict__ wqT,
            const float* __restrict__ Wk, __half* __restrict__ wkT,
            const float* __restrict__ Wv, __half* __restrict__ wvT,
            const float* __restrict__ Wo, __half* __restrict__ woT,
            const float* __restrict__ W1, __half* __restrict__ w1T,
            const float* __restrict__ W2, __half* __restrict__ w2T)
{
    __shared__ float t[64][33];
    const int tid = threadIdx.x;
    int b = blockIdx.x;

    if (b < 8192) {
        int i = b * 256 + tid;
        float4 v = ((const float4*)src)[i];
        __half2* o = (__half2*)src16;
        o[i * 2 + 0] = __floats2half2_rn(v.x, v.y);
        o[i * 2 + 1] = __floats2half2_rn(v.z, v.w);
        return;
    }
    b -= 8192;

    const float* inp; __half* outp; int Kd, Nd;
    if (b < 512)            { inp = Wq; outp = wqT; Kd = DDm; Nd = DHH; }
    else if (b < 1024)      { b -= 512;  inp = Wk; outp = wkT; Kd = DDm; Nd = DHH; }
    else if (b < 1536)      { b -= 1024; inp = Wv; outp = wvT; Kd = DDm; Nd = DHH; }
    else if (b < 2048)      { b -= 1536; inp = Wo; outp = woT; Kd = DDm; Nd = DDm; }
    else if (b < 4096)      { b -= 2048; inp = W1; outp = w1T; Kd = DDm; Nd = FFd; }
    else                    { b -= 4096; inp = W2; outp = w2T; Kd = FFd; Nd = DDm; }

    const int nx = Nd >> 5;
    const int ny = Kd >> 6;
    const int perz = nx * ny;
    const int z = b / perz;
    const int rem = b - z * perz;
    const int n0 = (rem % nx) * 32;
    const int k0 = (rem / nx) * 64;

    const float* inb = inp + (size_t)z * Kd * Nd;
    __half* outb = outp + (size_t)z * Nd * Kd;
    const int tx = tid & 31, ty = tid >> 5;

#pragma unroll
    for (int r = ty; r < 64; r += 8)
        t[r][tx] = inb[(size_t)(k0 + r) * Nd + n0 + tx];
    __syncthreads();

    const int c2 = tx * 2;
#pragma unroll
    for (int j = ty; j < 32; j += 8) {
        __half2 v = __floats2half2_rn(t[c2][j], t[c2 + 1][j]);
        *(__half2*)&outb[(size_t)(n0 + j) * Kd + k0 + c2] = v;
    }
}

// ---------------- fp16 tensor-core flash attention (3-buffer KV ring) -------
#define KROW 36
__global__ __launch_bounds__(256)
void fattn_k(const __half* __restrict__ Qg, const __half* __restrict__ Kg,
             const __half* __restrict__ Vt, __half* __restrict__ CTX)
{
    extern __shared__ uint32_t dsm[];
    uint32_t* sQ = dsm;
    uint32_t* sK = dsm + 128 * KROW;
    uint32_t* sV = dsm + 128 * KROW + 3 * 64 * KROW;

    const int b = blockIdx.z, h = blockIdx.y;
    const int q0 = blockIdx.x * 128;
    const int tid = threadIdx.x;
    const int warp = tid >> 5, lane = tid & 31;
    const int g = lane >> 2, t = lane & 3;

    const int krow = tid >> 2;
    const int keh  = (tid & 3) * 16;
    const int keb  = (tid & 3) * 8;

    {
        int row = tid >> 1, e0 = (tid & 1) * 32;
        const __half* src = Qg + (size_t)(b * SSQ + q0 + row) * DDm + h * DHH + e0;
        uint32_t dst = (uint32_t)__cvta_generic_to_shared(&sQ[row * KROW + (tid & 1) * 16]);
        CP_ASYNC16(dst,      src);
        CP_ASYNC16(dst + 16, src + 8);
        CP_ASYNC16(dst + 32, src + 16);
        CP_ASYNC16(dst + 48, src + 24);
    }
#define LOAD_TILE(buf, kv0) do { \
        uint32_t dk = (uint32_t)__cvta_generic_to_shared(&sK[(buf) * 64 * KROW + krow * KROW + keb]); \
        const __half* ks = Kg + (size_t)(b * SSQ + (kv0) + krow) * DDm + h * DHH + keh; \
        CP_ASYNC16(dk,      ks); \
        CP_ASYNC16(dk + 16, ks + 8); \
        uint32_t dv = (uint32_t)__cvta_generic_to_shared(&sV[(buf) * 64 * KROW + krow * KROW + keb]); \
        const __half* vs = Vt + (size_t)(h * DHH + krow) * BSr + (size_t)b * SSQ + (kv0) + keh; \
        CP_ASYNC16(dv,      vs); \
        CP_ASYNC16(dv + 16, vs + 8); \
    } while (0)

    LOAD_TILE(0, 0);
    CP_COMMIT();
    LOAD_TILE(1, 64);
    CP_COMMIT();

    CP_WAIT1();
    __syncthreads();

    uint32_t qa[4][4];
    {
        const uint32_t* sQw = sQ + (warp * 16) * KROW;
        const __half2 sc = __float2half2_rn(0.125f);
#pragma unroll
        for (int kc = 0; kc < 4; kc++) {
            int base = g * KROW + kc * 8 + t;
            qa[kc][0] = sQw[base];
            qa[kc][1] = sQw[base + 8 * KROW];
            qa[kc][2] = sQw[base + 4];
            qa[kc][3] = sQw[base + 8 * KROW + 4];
#pragma unroll
            for (int i = 0; i < 4; i++) {
                __half2 v = __hmul2(*(__half2*)&qa[kc][i], sc);
                qa[kc][i] = *(uint32_t*)&v;
            }
        }
    }

    float m0 = -1e30f, m1 = -1e30f, l0 = 0.0f, l1 = 0.0f;
    float o[8][4];
#pragma unroll
    for (int n = 0; n < 8; n++)
#pragma unroll
        for (int i = 0; i < 4; i++) o[n][i] = 0.0f;

    const int NIT = SSQ / 64;
    int cb3 = 0;
    for (int it = 0; it < NIT; it++) {
        CP_WAIT1();
        __syncthreads();

        if (it + 2 < NIT) {
            int lb = cb3 + 2; if (lb >= 3) lb -= 3;
            LOAD_TILE(lb, (it + 2) * 64);
        }
        CP_COMMIT();

        const uint32_t* kb = sK + cb3 * 64 * KROW;
        const uint32_t* vb = sV + cb3 * 64 * KROW;

        float acc[8][4];
#pragma unroll
        for (int n = 0; n < 8; n++)
#pragma unroll
            for (int i = 0; i < 4; i++) acc[n][i] = 0.0f;
#pragma unroll
        for (int kc = 0; kc < 4; kc++)
#pragma unroll
            for (int n = 0; n < 8; n++) {
                int base = (n * 8 + g) * KROW + kc * 8 + t;
                uint32_t b0 = kb[base];
                uint32_t b1 = kb[base + 4];
                MMA16816(acc[n], qa[kc], b0, b1);
            }

        float mx0 = -1e30f, mx1 = -1e30f;
#pragma unroll
        for (int n = 0; n < 8; n++) {
            mx0 = fmaxf(mx0, fmaxf(acc[n][0], acc[n][1]));
            mx1 = fmaxf(mx1, fmaxf(acc[n][2], acc[n][3]));
        }
        mx0 = fmaxf(mx0, __shfl_xor_sync(0xffffffffu, mx0, 1));
        mx0 = fmaxf(mx0, __shfl_xor_sync(0xffffffffu, mx0, 2));
        mx1 = fmaxf(mx1, __shfl_xor_sync(0xffffffffu, mx1, 1));
        mx1 = fmaxf(mx1, __shfl_xor_sync(0xffffffffu, mx1, 2));
        float nm0 = fmaxf(m0, mx0), nm1 = fmaxf(m1, mx1);
        float c0 = __expf(m0 - nm0), c1 = __expf(m1 - nm1);

        uint32_t pa[4][4];
        float s0 = 0.0f, s1 = 0.0f;
#pragma unroll
        for (int n = 0; n < 8; n++) {
            float p00 = __expf(acc[n][0] - nm0);
            float p01 = __expf(acc[n][1] - nm0);
            float p10 = __expf(acc[n][2] - nm1);
            float p11 = __expf(acc[n][3] - nm1);
            s0 += p00 + p01;
            s1 += p10 + p11;
            __half2 h0 = __floats2half2_rn(p00, p01);
            __half2 h1 = __floats2half2_rn(p10, p11);
            if (n & 1) {
                pa[n >> 1][2] = *(uint32_t*)&h0;
                pa[n >> 1][3] = *(uint32_t*)&h1;
            } else {
                pa[n >> 1][0] = *(uint32_t*)&h0;
                pa[n >> 1][1] = *(uint32_t*)&h1;
            }
        }
        s0 += __shfl_xor_sync(0xffffffffu, s0, 1);
        s0 += __shfl_xor_sync(0xffffffffu, s0, 2);
        s1 += __shfl_xor_sync(0xffffffffu, s1, 1);
        s1 += __shfl_xor_sync(0xffffffffu, s1, 2);
        l0 = l0 * c0 + s0;
        l1 = l1 * c1 + s1;
        m0 = nm0; m1 = nm1;
#pragma unroll
        for (int n = 0; n < 8; n++) {
            o[n][0] *= c0; o[n][1] *= c0;
            o[n][2] *= c1; o[n][3] *= c1;
        }

#pragma unroll
        for (int kc = 0; kc < 4; kc++)
#pragma unroll
            for (int n = 0; n < 8; n++) {
                int base = (n * 8 + g) * KROW + kc * 8 + t;
                uint32_t b0 = vb[base];
                uint32_t b1 = vb[base + 4];
                MMA16816(o[n], pa[kc], b0, b1);
            }

        if (++cb3 == 3) cb3 = 0;
    }

    float i0 = 1.0f / l0, i1 = 1.0f / l1;
    int r0 = b * SSQ + q0 + warp * 16 + g;
#pragma unroll
    for (int n = 0; n < 8; n++) {
        int col = h * DHH + n * 8 + t * 2;
        __half2 h0 = __floats2half2_rn(o[n][0] * i0, o[n][1] * i0);
        __half2 h1 = __floats2half2_rn(o[n][2] * i1, o[n][3] * i1);
        *(__half2*)&CTX[(size_t)r0 * DDm + col]       = h0;
        *(__half2*)&CTX[(size_t)(r0 + 8) * DDm + col] = h1;
    }
}

// ---------------- LayerNorm: warp-per-row, sync-free ------------------------
template<int OUT32, int OUT16>
__global__ __launch_bounds__(256)
void ln_k(const float* __restrict__ in, const float* __restrict__ w,
          const float* __restrict__ bb, float* __restrict__ out32,
          __half* __restrict__ out16)
{
    const int row  = blockIdx.x * 8 + (threadIdx.x >> 5);
    const int lane = threadIdx.x & 31;
    const float4* inr = (const float4*)(in + (size_t)row * DDm);

    float4 x[8];
    float s = 0.0f;
#pragma unroll
    for (int i = 0; i < 8; i++) {
        x[i] = inr[lane + i * 32];
        s += x[i].x + x[i].y + x[i].z + x[i].w;
    }
#pragma unroll
    for (int off = 16; off; off >>= 1) s += __shfl_xor_sync(0xffffffffu, s, off);
    float mean = s * (1.0f / DDm);

    float sq = 0.0f;
#pragma unroll
    for (int i = 0; i < 8; i++) {
        float d0 = x[i].x - mean, d1 = x[i].y - mean;
        float d2 = x[i].z - mean, d3 = x[i].w - mean;
        sq += d0 * d0 + d1 * d1 + d2 * d2 + d3 * d3;
    }
#pragma unroll
    for (int off = 16; off; off >>= 1) sq += __shfl_xor_sync(0xffffffffu, sq, off);
    float rs = rsqrtf(sq * (1.0f / DDm) + EPSLN);

    const float4* w4 = (const float4*)w;
    const float4* b4 = (const float4*)bb;
#pragma unroll
    for (int i = 0; i < 8; i++) {
        int c4 = lane + i * 32;
        float4 wv = w4[c4];
        float4 bv = b4[c4];
        float y0 = (x[i].x - mean) * rs * wv.x + bv.x;
        float y1 = (x[i].y - mean) * rs * wv.y + bv.y;
        float y2 = (x[i].z - mean) * rs * wv.z + bv.z;
        float y3 = (x[i].w - mean) * rs * wv.w + bv.w;
        if (OUT32)
            ((float4*)(out32 + (size_t)row * DDm))[c4] = make_float4(y0, y1, y2, y3);
        if (OUT16) {
            __half2* o2 = (__half2*)(out16 + (size_t)row * DDm) + c4 * 2;
            o2[0] = __floats2half2_rn(y0, y1);
            o2[1] = __floats2half2_rn(y2, y3);
        }
    }
}

// ---------------------------- launch ---------------------------------------
extern "C" void kernel_launch(void* const* d_in, const int* in_sizes, int n_in,
                              void* d_out, int out_size)
{
    const float* src   = (const float*)d_in[0];
    const float* Wq    = (const float*)d_in[1];
    const float* bq    = (const float*)d_in[2];
    const float* Wk    = (const float*)d_in[3];
    const float* bk    = (const float*)d_in[4];
    const float* Wv    = (const float*)d_in[5];
    const float* bv    = (const float*)d_in[6];
    const float* Wo    = (const float*)d_in[7];
    const float* bo    = (const float*)d_in[8];
    const float* ln1w  = (const float*)d_in[9];
    const float* ln1b  = (const float*)d_in[10];
    const float* W1    = (const float*)d_in[11];
    const float* b1    = (const float*)d_in[12];
    const float* W2    = (const float*)d_in[13];
    const float* b2    = (const float*)d_in[14];
    const float* ln2w  = (const float*)d_in[15];
    const float* ln2b  = (const float*)d_in[16];
    float* out = (float*)d_out;

    float *py1, *py2;
    __half *psrc16, *pq16, *pk16, *pvT16, *pctx16, *px16, *ph16;
    __half *pwqT, *pwkT, *pwvT, *pwoT, *pw1T, *pw2T;
    cudaGetSymbolAddress((void**)&py1,   g_y1);
    cudaGetSymbolAddress((void**)&py2,   g_y2);
    cudaGetSymbolAddress((void**)&psrc16, g_src16);
    cudaGetSymbolAddress((void**)&pq16,   g_q16);
    cudaGetSymbolAddress((void**)&pk16,   g_k16);
    cudaGetSymbolAddress((void**)&pvT16,  g_vT16);
    cudaGetSymbolAddress((void**)&pctx16, g_ctx16);
    cudaGetSymbolAddress((void**)&px16,   g_x16);
    cudaGetSymbolAddress((void**)&ph16,   g_h16);
    cudaGetSymbolAddress((void**)&pwqT,   g_wqT);
    cudaGetSymbolAddress((void**)&pwkT,   g_wkT);
    cudaGetSymbolAddress((void**)&pwvT,   g_wvT);
    cudaGetSymbolAddress((void**)&pwoT,   g_woT);
    cudaGetSymbolAddress((void**)&pw1T,   g_w1T);
    cudaGetSymbolAddress((void**)&pw2T,   g_w2T);

    const int ATTN_SMEM = (128 * KROW + 6 * 64 * KROW) * sizeof(uint32_t);
    cudaFuncSetAttribute(fattn_k, cudaFuncAttributeMaxDynamicSharedMemorySize, ATTN_SMEM);
    cudaFuncSetAttribute(hgemm_qkv_k, cudaFuncAttributeMaxDynamicSharedMemorySize, HG_SMEM);
    cudaFuncSetAttribute(hgemm_k<0,1,1,0>, cudaFuncAttributeMaxDynamicSharedMemorySize, HG_SMEM);
    cudaFuncSetAttribute(hgemm_k<1,0,0,1>, cudaFuncAttributeMaxDynamicSharedMemorySize, HG_SMEM);
    cudaFuncSetAttribute(hgemm_k<0,2,1,0>, cudaFuncAttributeMaxDynamicSharedMemorySize, HG_SMEM);

    dim3 thr(256);
    dim3 gD(DDm / 128, BSr / 128);        // (8, 64)
    dim3 gF(FFd / 128, BSr / 128);        // (32, 64)
    dim3 gQKV(DDm / 128, BSr / 128, 3);   // (8, 64, 3)

    // ---- fused prep (one launch) ----
    prep_k<<<14336, thr>>>(src, psrc16, Wq, pwqT, Wk, pwkT, Wv, pwvT,
                           Wo, pwoT, W1, pw1T, W2, pw2T);

    // ---- merged QKV projections (one launch) ----
    hgemm_qkv_k<<<gQKV, thr, HG_SMEM>>>(psrc16, pwqT, pwkT, pwvT,
                                        bq, bk, bv, pq16, pk16, pvT16);

    // ---- flash attention ----
    dim3 gAttn(SSQ / 128, HHn, BB);
    fattn_k<<<gAttn, thr, ATTN_SMEM>>>(pq16, pk16, pvT16, pctx16);

    // ---- output projection + residual, LN1 ----
    hgemm_k<0,1,1,0><<<gD, thr, HG_SMEM>>>(pctx16, pwoT, bo, src, py1, nullptr, BSr, DDm, DDm);
    ln_k<0,1><<<BSr / 8, thr>>>(py1, ln1w, ln1b, nullptr, px16);

    // ---- FFN ----
    hgemm_k<1,0,0,1><<<gF, thr, HG_SMEM>>>(px16, pw1T, b1, nullptr, nullptr, ph16, BSr, FFd, DDm);
    hgemm_k<0,2,1,0><<<gD, thr, HG_SMEM>>>(ph16, pw2T, b2, px16, py2, nullptr, BSr, DDm, FFd);
    ln_k<1,0><<<BSr / 8, thr>>>(py2, ln2w, ln2b, out, nullptr);
}